// round 17
// baseline (speedup 1.0000x reference)
#include <cuda_runtime.h>
#include <cuda_fp16.h>
#include <stdint.h>
#include <math.h>

// Problem constants
#define BB      4
#define SS      4096
#define DD      768
#define NHH     8
#define PROJ    512          // NH*DK = NH*DV
#define NTOK    16384        // B*S
#define CHUNK   128
#define NC      32           // S / CHUNK
#define STATE_SZ 32768       // NH*DK*DV

// ---------------- device scratch (static, no allocation) ----------------
__device__ __half g_wkh [PROJ * DD];
__device__ __half g_wvh [PROJ * DD];
__device__ __half g_wqh [PROJ * DD];
__device__ __half g_wgh [NHH * DD];
__device__ __half g_woh [DD * PROJ];
__device__ __half g_qh  [NTOK * PROJ];     // q (all batches), fp16
__device__ __half g_k0h [SS * PROJ];       // k batch 0, fp16
__device__ __half g_v0h [SS * PROJ];       // v batch 0, fp16
__device__ __half g_retrh[NTOK * PROJ];    // retrieved, fp16
__device__ float  g_g0  [SS * NHH];
__device__ float  g_W   [NC * STATE_SZ];
__device__ float  g_Fst [NC * STATE_SZ];
__device__ float  g_dpow[136];

// ---------------- convert f32 weights -> fp16 (+ dpow table) ----------------
#define WN  (PROJ * DD)
#define GN  (NHH * DD)
#define CV_TOT4 ((4 * WN + GN) / 4)

__global__ void convert_kernel(
    const float* __restrict__ wk, const float* __restrict__ wv,
    const float* __restrict__ wq, const float* __restrict__ wg,
    const float* __restrict__ wo)
{
    if (blockIdx.x == 0 && threadIdx.x == 0) {
        double p = 1.0;
        for (int i = 0; i <= 128; i++) { g_dpow[i] = (float)p; p *= 0.95; }
    }
    size_t stride = (size_t)gridDim.x * blockDim.x;
    for (size_t i = blockIdx.x * (size_t)blockDim.x + threadIdx.x;
         i < CV_TOT4; i += stride) {
        size_t e = i * 4;
        const float* src; __half* dst; size_t off;
        if      (e < WN)               { src = wk; dst = g_wkh; off = e; }
        else if (e < 2 * WN)           { src = wv; dst = g_wvh; off = e - WN; }
        else if (e < 3 * WN)           { src = wq; dst = g_wqh; off = e - 2 * WN; }
        else if (e < 3 * WN + GN)      { src = wg; dst = g_wgh; off = e - 3 * WN; }
        else                           { src = wo; dst = g_woh; off = e - 3 * WN - GN; }
        float4 v = *(const float4*)(src + off);
        *(__half2*)(dst + off)     = __floats2half2_rn(v.x, v.y);
        *(__half2*)(dst + off + 2) = __floats2half2_rn(v.z, v.w);
    }
}

// ---------------- tensor-core plumbing (fp16 m16n8k16; tcgen05 unavailable:
// harness emits compute_103 PTX which ptxas rejects for tcgen05) ------------
#define MMA_F16(d, a, b)                                                      \
    asm volatile("mma.sync.aligned.m16n8k16.row.col.f32.f16.f16.f32 "         \
                 "{%0,%1,%2,%3}, {%4,%5,%6,%7}, {%8,%9}, {%0,%1,%2,%3};"      \
                 : "+f"((d)[0]), "+f"((d)[1]), "+f"((d)[2]), "+f"((d)[3])     \
                 : "r"((a)[0]), "r"((a)[1]), "r"((a)[2]), "r"((a)[3]),        \
                   "r"((b)[0]), "r"((b)[1]))

#define LDSM4(r0, r1, r2, r3, addr)                                           \
    asm volatile("ldmatrix.sync.aligned.m8n8.x4.shared.b16 {%0,%1,%2,%3}, [%4];" \
                 : "=r"(r0), "=r"(r1), "=r"(r2), "=r"(r3) : "r"(addr))

#define CP_ASYNC16(dst, src)                                                  \
    asm volatile("cp.async.cg.shared.global [%0], [%1], 16;" :: "r"(dst), "l"(src))
#define CP_COMMIT() asm volatile("cp.async.commit_group;")
#define CP_WAIT1()  asm volatile("cp.async.wait_group 1;")
#define CP_WAIT0()  asm volatile("cp.async.wait_group 0;")

// convert 8 f32 -> 8 fp16 and store 16B to shared (generic pointer -> STS)
__device__ __forceinline__ void cvt_sts16(char* dst, float4 a, float4 b)
{
    __half2 h0 = __floats2half2_rn(a.x, a.y);
    __half2 h1 = __floats2half2_rn(a.z, a.w);
    __half2 h2 = __floats2half2_rn(b.x, b.y);
    __half2 h3 = __floats2half2_rn(b.z, b.w);
    uint4 u = make_uint4(*(uint32_t*)&h0, *(uint32_t*)&h1,
                         *(uint32_t*)&h2, *(uint32_t*)&h3);
    *(uint4*)dst = u;
}

// ================= fp16 projection GEMM body =================
// 128x128 block, BK=32 (64B rows), 256 threads = 8 warps (2x4), warp 64x32.
// 3-stage pipeline. B always fp16 via cp.async. A either fp16 via cp.async
// (AFP32=0) or fp32 via register-staged LDG+cvt+STS (AFP32=1); the STS at
// iter it targets buffer (it+2)%3, last read at it-1 and ordered by the
// barrier at the top of iter it (BAR.SYNC drains STS).
#define TG_PB     80                           // pitch bytes
#define TG_BUFB   (128 * TG_PB)                // 10240 bytes per stage buffer
#define TG_SMEM   (6 * TG_BUFB)                // A[3] + B[3] = 61440 bytes

// mode 0: fp16 C store. mode 1: gate (sigmoid -> g_g0). mode 2: f32 C + Cadd.
template<int AFP32>
__device__ __forceinline__ void gemm_body(
    const void* __restrict__ Av, const __half* __restrict__ Bm,
    const float* __restrict__ Cadd, void* __restrict__ Cout,
    int N, int K, int bx, int by, int bmask, int mode)
{
    extern __shared__ char smg[];
    uint32_t sA = (uint32_t)__cvta_generic_to_shared(smg);
    uint32_t sB = sA + 3 * TG_BUFB;

    int t    = threadIdx.x;
    int warp = t >> 5, lane = t & 31;
    int wm = warp >> 2, wn = warp & 3;     // warp grid 2 x 4
    int g  = lane >> 3, gr = lane & 7;     // ldmatrix groups
    int lr = lane >> 2, lc = lane & 3;     // mma C-fragment decomposition

    // loader: 2 chunks of 16B(fp16) per matrix per thread per slab
    int r0c = t >> 2,        c0 = t & 3;           // chunk t
    int r1c = (t + 256) >> 2, c1 = (t + 256) & 3;  // chunk t+256
    const __half* gB0 = Bm + (size_t)(bx * 128 + (r0c & bmask)) * K + c0 * 8;
    const __half* gB1 = Bm + (size_t)(bx * 128 + (r1c & bmask)) * K + c1 * 8;
    uint32_t offA0 = (uint32_t)(r0c * TG_PB + c0 * 16);
    uint32_t offA1 = (uint32_t)(r1c * TG_PB + c1 * 16);
    uint32_t dB0 = sB + (uint32_t)(r0c * TG_PB + c0 * 16);
    uint32_t dB1 = sB + (uint32_t)(r1c * TG_PB + c1 * 16);

    const __half* gA0h = (const __half*)Av + (size_t)(by * 128 + r0c) * K + c0 * 8;
    const __half* gA1h = (const __half*)Av + (size_t)(by * 128 + r1c) * K + c1 * 8;
    const float*  gA0f = (const float*)Av + (size_t)(by * 128 + r0c) * K + c0 * 8;
    const float*  gA1f = (const float*)Av + (size_t)(by * 128 + r1c) * K + c1 * 8;
    uint32_t dA0 = sA + offA0;
    uint32_t dA1 = sA + offA1;

    uint32_t aAddr[4];
#pragma unroll
    for (int mt = 0; mt < 4; mt++)
        aAddr[mt] = sA + (uint32_t)((wm * 64 + mt * 16 + (g & 1) * 8 + gr) * TG_PB
                                     + (g >> 1) * 16);
    uint32_t bAddr[2];
#pragma unroll
    for (int np = 0; np < 2; np++)
        bAddr[np] = sB + (uint32_t)((wn * 32 + (2 * np + (g >> 1)) * 8 + gr) * TG_PB
                                     + (g & 1) * 16);

    float acc[4][4][4];
#pragma unroll
    for (int i = 0; i < 4; i++)
#pragma unroll
        for (int j = 0; j < 4; j++)
#pragma unroll
            for (int r = 0; r < 4; r++) acc[i][j][r] = 0.f;

    const int NIT = K >> 5;
    float4 stg0a, stg0b, stg1a, stg1b;     // staged fp32 A regs (AFP32 path)

    // prologue: slabs 0 and 1
    if (AFP32) {
#pragma unroll
        for (int s = 0; s < 2; s++) {
            int ko = s * 32;
            cvt_sts16(smg + s * TG_BUFB + offA0,
                      *(const float4*)(gA0f + ko), *(const float4*)(gA0f + ko + 4));
            cvt_sts16(smg + s * TG_BUFB + offA1,
                      *(const float4*)(gA1f + ko), *(const float4*)(gA1f + ko + 4));
        }
        if (NIT > 2) {                     // stage slab 2
            stg0a = *(const float4*)(gA0f + 64); stg0b = *(const float4*)(gA0f + 68);
            stg1a = *(const float4*)(gA1f + 64); stg1b = *(const float4*)(gA1f + 68);
        }
        CP_ASYNC16(dB0, gB0); CP_ASYNC16(dB1, gB1);
        CP_COMMIT();
        CP_ASYNC16(dB0 + TG_BUFB, gB0 + 32); CP_ASYNC16(dB1 + TG_BUFB, gB1 + 32);
        CP_COMMIT();
    } else {
        CP_ASYNC16(dA0, gA0h); CP_ASYNC16(dA1, gA1h);
        CP_ASYNC16(dB0, gB0);  CP_ASYNC16(dB1, gB1);
        CP_COMMIT();
        CP_ASYNC16(dA0 + TG_BUFB, gA0h + 32); CP_ASYNC16(dA1 + TG_BUFB, gA1h + 32);
        CP_ASYNC16(dB0 + TG_BUFB, gB0 + 32);  CP_ASYNC16(dB1 + TG_BUFB, gB1 + 32);
        CP_COMMIT();
    }

    int st = 0, st2 = 2;
    for (int it = 0; it < NIT; it++) {
        if (it < NIT - 1) CP_WAIT1(); else CP_WAIT0();
        __syncthreads();

        if (it + 2 < NIT) {
            int ko = (it + 2) * 32;
            uint32_t o2 = (uint32_t)st2 * TG_BUFB;
            if (AFP32) {
                cvt_sts16(smg + o2 + offA0, stg0a, stg0b);
                cvt_sts16(smg + o2 + offA1, stg1a, stg1b);
                if (it + 3 < NIT) {
                    int k3 = (it + 3) * 32;
                    stg0a = *(const float4*)(gA0f + k3); stg0b = *(const float4*)(gA0f + k3 + 4);
                    stg1a = *(const float4*)(gA1f + k3); stg1b = *(const float4*)(gA1f + k3 + 4);
                }
            } else {
                CP_ASYNC16(dA0 + o2, gA0h + ko); CP_ASYNC16(dA1 + o2, gA1h + ko);
            }
            CP_ASYNC16(dB0 + o2, gB0 + ko); CP_ASYNC16(dB1 + o2, gB1 + ko);
            CP_COMMIT();
        }

        uint32_t oa = (uint32_t)st * TG_BUFB;
#pragma unroll
        for (int ks = 0; ks < 2; ks++) {           // k16 per step, 32B stride
            uint32_t af[4][4];
#pragma unroll
            for (int mt = 0; mt < 4; mt++)
                LDSM4(af[mt][0], af[mt][1], af[mt][2], af[mt][3],
                      aAddr[mt] + oa + ks * 32);
            uint32_t bf[4][2];
#pragma unroll
            for (int np = 0; np < 2; np++)
                LDSM4(bf[2 * np][0], bf[2 * np][1], bf[2 * np + 1][0], bf[2 * np + 1][1],
                      bAddr[np] + oa + ks * 32);
#pragma unroll
            for (int mt = 0; mt < 4; mt++)
#pragma unroll
                for (int nt = 0; nt < 4; nt++)
                    MMA_F16(acc[mt][nt], af[mt], bf[nt]);
        }

        st  = (st  == 2) ? 0 : st  + 1;
        st2 = (st2 == 2) ? 0 : st2 + 1;
    }

    if (mode == 1) {
        if (wn == 0) {
#pragma unroll
            for (int mt = 0; mt < 4; mt++) {
                int r = by * 128 + wm * 64 + mt * 16 + lr;
                int c = 2 * lc;                     // 0..7 == head index
                g_g0[r * NHH + c]           = 1.f / (1.f + expf(-acc[mt][0][0]));
                g_g0[r * NHH + c + 1]       = 1.f / (1.f + expf(-acc[mt][0][1]));
                g_g0[(r + 8) * NHH + c]     = 1.f / (1.f + expf(-acc[mt][0][2]));
                g_g0[(r + 8) * NHH + c + 1] = 1.f / (1.f + expf(-acc[mt][0][3]));
            }
        }
        return;
    }

#pragma unroll
    for (int mt = 0; mt < 4; mt++) {
#pragma unroll
        for (int nt = 0; nt < 4; nt++) {
            int r = by * 128 + wm * 64 + mt * 16 + lr;
            int c = bx * 128 + wn * 32 + nt * 8 + 2 * lc;
            size_t off0 = (size_t)r * N + c;
            size_t off1 = (size_t)(r + 8) * N + c;
            if (mode == 0) {
                __half* Ch = (__half*)Cout;
                *(__half2*)(Ch + off0) = __floats2half2_rn(acc[mt][nt][0], acc[mt][nt][1]);
                *(__half2*)(Ch + off1) = __floats2half2_rn(acc[mt][nt][2], acc[mt][nt][3]);
            } else {
                float* Cf = (float*)Cout;
                float2 lo = make_float2(acc[mt][nt][0], acc[mt][nt][1]);
                float2 hi = make_float2(acc[mt][nt][2], acc[mt][nt][3]);
                float2 x0 = *(const float2*)(Cadd + off0);
                float2 x1 = *(const float2*)(Cadd + off1);
                lo.x += x0.x; lo.y += x0.y; hi.x += x1.x; hi.y += x1.y;
                *(float2*)(Cf + off0) = lo;
                *(float2*)(Cf + off1) = hi;
            }
        }
    }
}

// out-projection: out = x + retr @ wo^T (f32 result)
__global__ void __launch_bounds__(256, 2) tgemm_out(
    const float* __restrict__ x, float* __restrict__ out)
{
    gemm_body<0>(g_retrh, g_woh, x, out, DD, PROJ, blockIdx.x, blockIdx.y, 127, 2);
}

// merged front-end: q-proj (512 blocks) + k/v-proj (256) + gate (32).
// A = x read directly as fp32 (in-loader conversion).
__global__ void __launch_bounds__(256, 2) proj_all(const float* __restrict__ x)
{
    int bid = blockIdx.x;
    if (bid < 512) {
        gemm_body<1>(x, g_wqh, nullptr, g_qh, PROJ, DD, bid & 3, bid >> 2, 127, 0);
    } else if (bid < 768) {
        int i = bid - 512;
        int bx = i & 7, by = i >> 3;
        int sel = bx >> 2;
        gemm_body<1>(x, sel ? g_wvh : g_wkh, nullptr, sel ? g_v0h : g_k0h,
                     PROJ, DD, bx & 3, by, 127, 0);
    } else {
        gemm_body<1>(x, g_wgh, nullptr, nullptr, NHH, DD, 0, bid - 768, 7, 1);
    }
}

// ---------------- per-chunk decayed write sum ----------------
__global__ __launch_bounds__(256) void chunkw_kernel()
{
    __shared__ float Ks[32][68];
    __shared__ float Vs[32][68];
    int h = blockIdx.x, c = blockIdx.y;
    int t = threadIdx.x, tx = t & 15, ty = t >> 4;

    float acc[4][4];
#pragma unroll
    for (int i = 0; i < 4; i++)
#pragma unroll
        for (int j = 0; j < 4; j++) acc[i][j] = 0.f;

    for (int jt = 0; jt < 4; jt++) {
        {
            int j = t >> 3, kk8 = (t & 7) * 8;
            int row = c * CHUNK + jt * 32 + j;
            float s = g_dpow[127 - (jt * 32 + j)] * 0.1f * g_g0[row * NHH + h];
            union { uint4 u; __half hh[8]; } kv, vv;
            kv.u = *(const uint4*)(g_k0h + (size_t)row * PROJ + h * 64 + kk8);
            vv.u = *(const uint4*)(g_v0h + (size_t)row * PROJ + h * 64 + kk8);
#pragma unroll
            for (int q = 0; q < 8; q++) {
                Ks[j][kk8 + q] = __half2float(kv.hh[q]) * s;
                Vs[j][kk8 + q] = __half2float(vv.hh[q]);
            }
        }
        __syncthreads();
#pragma unroll
        for (int j = 0; j < 32; j++) {
            float kr[4], vr[4];
            *(float4*)kr = *(const float4*)&Ks[j][ty * 4];
            *(float4*)vr = *(const float4*)&Vs[j][tx * 4];
#pragma unroll
            for (int ii = 0; ii < 4; ii++)
#pragma unroll
                for (int jj = 0; jj < 4; jj++)
                    acc[ii][jj] += kr[ii] * vr[jj];
        }
        __syncthreads();
    }
#pragma unroll
    for (int ii = 0; ii < 4; ii++) {
        float4 o = make_float4(acc[ii][0], acc[ii][1], acc[ii][2], acc[ii][3]);
        *(float4*)(g_W + ((size_t)(c * NHH + h) * 64 + ty * 4 + ii) * 64 + tx * 4) = o;
    }
}

// ---------------- state prefix scan over chunks (MLP x8) ----------------
__global__ void scan_kernel()
{
    int e = blockIdx.x * blockDim.x + threadIdx.x;
    float fw = 0.f;
    const float dc = g_dpow[128];
#pragma unroll
    for (int c = 0; c < NC; c += 8) {
        float w[8];
#pragma unroll
        for (int u = 0; u < 8; u++)
            w[u] = g_W[(size_t)(c + u) * STATE_SZ + e];
#pragma unroll
        for (int u = 0; u < 8; u++) {
            g_Fst[(size_t)(c + u) * STATE_SZ + e] = fw;
            fw = dc * fw + w[u];
        }
    }
}

// ================= fp16 tensor-core retrieval =================
// Full K/V chunk preloaded once; masked-A double buffered -> ONE sync per jt.
// dpow table copied to shared (sdp) — mask epilogue reads LDS, not LDG.
#define RP64  72                               // halves
#define VPH   136                              // halves (272B)
#define APH   40                               // halves (80B)
#define RS_QS 0
#define RS_FT (RS_QS + 128 * 144)              // 18432
#define RS_KT (RS_FT + 64 * 144)               // 27648
#define RS_VT (RS_KT + 128 * 144)              // 46080
#define RS_AS (RS_VT + 64 * 272)               // 63488
#define AS_BUFB (128 * 80)                     // 10240 per buffer
#define RS_SG (RS_AS + 2 * AS_BUFB)            // 83968
#define RS_DP (RS_SG + 512)                    // 84480
#define RT_SMEM (RS_DP + 576)                  // 85056 bytes

__global__ void __launch_bounds__(256, 2) retrieve_tc()
{
    extern __shared__ char smr[];
    uint32_t sbase = (uint32_t)__cvta_generic_to_shared(smr);
    __half* Qs = (__half*)(smr + RS_QS);
    __half* Ft = (__half*)(smr + RS_FT);
    __half* Kt = (__half*)(smr + RS_KT);
    __half* Vt = (__half*)(smr + RS_VT);
    __half* As = (__half*)(smr + RS_AS);
    float*  sg = (float*)(smr + RS_SG);
    float*  sdp = (float*)(smr + RS_DP);

    int h = blockIdx.x, c = blockIdx.y, b = blockIdx.z;
    int t = threadIdx.x;
    int warp = t >> 5, lane = t & 31;
    int wr = warp >> 1, wc = warp & 1;         // 4 x 2 warp grid
    int g  = lane >> 3, gr = lane & 7;
    int lr = lane >> 2, lc = lane & 3;

    // ---- preload everything, one sync ----
#pragma unroll
    for (int i = 0; i < 4; i++) {
        int p = t + 256 * i;
        int row = p >> 3, c8 = (p & 7) * 8;
        *(uint4*)(Qs + row * RP64 + c8) =
            *(const uint4*)(g_qh + (size_t)(b * SS + c * CHUNK + row) * PROJ + h * 64 + c8);
    }
#pragma unroll
    for (int i = 0; i < 4; i++) {
        int p = t + 256 * i;
        int k = p >> 4, v4 = (p & 15) * 4;
        float4 v = *(const float4*)(g_Fst + (size_t)c * STATE_SZ + h * 4096 + k * 64 + v4);
        Ft[(v4 + 0) * RP64 + k] = __float2half(v.x);
        Ft[(v4 + 1) * RP64 + k] = __float2half(v.y);
        Ft[(v4 + 2) * RP64 + k] = __float2half(v.z);
        Ft[(v4 + 3) * RP64 + k] = __float2half(v.w);
    }
#pragma unroll
    for (int i = 0; i < 4; i++) {
        int p = t + 256 * i;
        int row = p >> 3, c8 = (p & 7) * 8;
        *(uint4*)(Kt + row * RP64 + c8) =
            *(const uint4*)(g_k0h + (size_t)(c * CHUNK + row) * PROJ + h * 64 + c8);
    }
#pragma unroll
    for (int i = 0; i < 4; i++) {
        int p = t + 256 * i;
        int j = p >> 3, kk8 = (p & 7) * 8;
        union { uint4 u; __half hh[8]; } vv;
        vv.u = *(const uint4*)(g_v0h + (size_t)(c * CHUNK + j) * PROJ + h * 64 + kk8);
#pragma unroll
        for (int q = 0; q < 8; q++)
            Vt[(kk8 + q) * VPH + j] = vv.hh[q];
    }
    if (t < 128) sg[t] = 0.1f * g_g0[(c * CHUNK + t) * NHH + h];
    if (t < 136) sdp[t] = g_dpow[t];
    __syncthreads();

    uint32_t qA[2], aA[2], fB[2], vB[2], kB;
#pragma unroll
    for (int mt = 0; mt < 2; mt++) {
        qA[mt] = sbase + (uint32_t)(RS_QS + (wr * 32 + mt * 16 + (g & 1) * 8 + gr) * 144
                                    + (g >> 1) * 16);
        aA[mt] = sbase + (uint32_t)(RS_AS + (wr * 32 + mt * 16 + (g & 1) * 8 + gr) * 80
                                    + (g >> 1) * 16);
    }
#pragma unroll
    for (int np = 0; np < 2; np++) {
        fB[np] = sbase + (uint32_t)(RS_FT + (wc * 32 + (2 * np + (g >> 1)) * 8 + gr) * 144
                                    + (g & 1) * 16);
        vB[np] = sbase + (uint32_t)(RS_VT + (wc * 32 + (2 * np + (g >> 1)) * 8 + gr) * 272
                                    + (g & 1) * 16);
    }
    kB = sbase + (uint32_t)(RS_KT + (wc * 16 + (g >> 1) * 8 + gr) * 144 + (g & 1) * 16);

    float racc[2][4][4];
#pragma unroll
    for (int i = 0; i < 2; i++)
#pragma unroll
        for (int j = 0; j < 4; j++)
#pragma unroll
            for (int r = 0; r < 4; r++) racc[i][j][r] = 0.f;

    // inter-chunk: R = Q @ F  (K=64 -> 4 k16 steps)
#pragma unroll
    for (int ks = 0; ks < 4; ks++) {
        uint32_t af[2][4], bf[4][2];
#pragma unroll
        for (int mt = 0; mt < 2; mt++)
            LDSM4(af[mt][0], af[mt][1], af[mt][2], af[mt][3], qA[mt] + ks * 32);
#pragma unroll
        for (int np = 0; np < 2; np++)
            LDSM4(bf[2 * np][0], bf[2 * np][1], bf[2 * np + 1][0], bf[2 * np + 1][1],
                  fB[np] + ks * 32);
#pragma unroll
        for (int mt = 0; mt < 2; mt++)
#pragma unroll
            for (int nt = 0; nt < 4; nt++)
                MMA_F16(racc[mt][nt], af[mt], bf[nt]);
    }
#pragma unroll
    for (int mt = 0; mt < 2; mt++) {
        int r0 = wr * 32 + mt * 16 + lr;
        float l0 = sdp[r0], l1 = sdp[r0 + 8];
#pragma unroll
        for (int nt = 0; nt < 4; nt++) {
            racc[mt][nt][0] *= l0; racc[mt][nt][1] *= l0;
            racc[mt][nt][2] *= l1; racc[mt][nt][3] *= l1;
        }
    }

    // intra-chunk: 4 key-tiles of 32; one __syncthreads per tile.
    for (int jt = 0; jt < 4; jt++) {
        uint32_t asOff = (uint32_t)(jt & 1) * AS_BUFB;

        float qk[2][2][4];
#pragma unroll
        for (int i = 0; i < 2; i++)
#pragma unroll
            for (int j = 0; j < 2; j++)
#pragma unroll
                for (int r = 0; r < 4; r++) qk[i][j][r] = 0.f;
        uint32_t kOff = (uint32_t)jt * (32 * 144);
#pragma unroll
        for (int ks = 0; ks < 4; ks++) {
            uint32_t af[2][4], bf[2][2];
#pragma unroll
            for (int mt = 0; mt < 2; mt++)
                LDSM4(af[mt][0], af[mt][1], af[mt][2], af[mt][3], qA[mt] + ks * 32);
            LDSM4(bf[0][0], bf[0][1], bf[1][0], bf[1][1], kB + kOff + ks * 32);
#pragma unroll
            for (int mt = 0; mt < 2; mt++)
#pragma unroll
                for (int nt = 0; nt < 2; nt++)
                    MMA_F16(qk[mt][nt], af[mt], bf[nt]);
        }

        __half* Asb = (__half*)((char*)As + asOff);
#pragma unroll
        for (int mt = 0; mt < 2; mt++) {
            int i0 = wr * 32 + mt * 16 + lr, i1 = i0 + 8;
#pragma unroll
            for (int nt = 0; nt < 2; nt++) {
                int jl = wc * 16 + nt * 8 + 2 * lc;
                int jg0 = jt * 32 + jl, jg1 = jg0 + 1;
                float w0, w1, w2, w3;
                w0 = (jg0 < i0) ? sdp[i0 - 1 - jg0] * sg[jg0] : 0.f;
                w1 = (jg1 < i0) ? sdp[i0 - 1 - jg1] * sg[jg1] : 0.f;
                w2 = (jg0 < i1) ? sdp[i1 - 1 - jg0] * sg[jg0] : 0.f;
                w3 = (jg1 < i1) ? sdp[i1 - 1 - jg1] * sg[jg1] : 0.f;
                *(__half2*)(Asb + i0 * APH + jl) =
                    __floats2half2_rn(qk[mt][nt][0] * w0, qk[mt][nt][1] * w1);
                *(__half2*)(Asb + i1 * APH + jl) =
                    __floats2half2_rn(qk[mt][nt][2] * w2, qk[mt][nt][3] * w3);
            }
        }
        __syncthreads();

        uint32_t vOff = (uint32_t)jt * 64;
#pragma unroll
        for (int ks = 0; ks < 2; ks++) {
            uint32_t af[2][4], bf[4][2];
#pragma unroll
            for (int mt = 0; mt < 2; mt++)
                LDSM4(af[mt][0], af[mt][1], af[mt][2], af[mt][3],
                      aA[mt] + asOff + ks * 32);
#pragma unroll
            for (int np = 0; np < 2; np++)
                LDSM4(bf[2 * np][0], bf[2 * np][1], bf[2 * np + 1][0], bf[2 * np + 1][1],
                      vB[np] + vOff + ks * 32);
#pragma unroll
            for (int mt = 0; mt < 2; mt++)
#pragma unroll
                for (int nt = 0; nt < 4; nt++)
                    MMA_F16(racc[mt][nt], af[mt], bf[nt]);
        }
    }

    // store R as fp16
#pragma unroll
    for (int mt = 0; mt < 2; mt++) {
#pragma unroll
        for (int nt = 0; nt < 4; nt++) {
            int i = wr * 32 + mt * 16 + lr;
            int v = wc * 32 + nt * 8 + 2 * lc;
            size_t off0 = (size_t)(b * SS + c * CHUNK + i) * PROJ + h * 64 + v;
            size_t off1 = (size_t)(b * SS + c * CHUNK + i + 8) * PROJ + h * 64 + v;
            *(__half2*)(g_retrh + off0) = __floats2half2_rn(racc[mt][nt][0], racc[mt][nt][1]);
            *(__half2*)(g_retrh + off1) = __floats2half2_rn(racc[mt][nt][2], racc[mt][nt][3]);
        }
    }
}

// ---------------- host launch ----------------
extern "C" void kernel_launch(void* const* d_in, const int* in_sizes, int n_in,
                              void* d_out, int out_size)
{
    (void)in_sizes; (void)n_in; (void)out_size;
    const float* x  = (const float*)d_in[0];
    const float* wk = (const float*)d_in[1];
    const float* wv = (const float*)d_in[2];
    const float* wq = (const float*)d_in[3];
    const float* wg = (const float*)d_in[4];
    const float* wo = (const float*)d_in[5];
    float* out = (float*)d_out;

    cudaFuncSetAttribute(retrieve_tc,
                         cudaFuncAttributeMaxDynamicSharedMemorySize, RT_SMEM);
    cudaFuncSetAttribute(tgemm_out,
                         cudaFuncAttributeMaxDynamicSharedMemorySize, TG_SMEM);
    cudaFuncSetAttribute(proj_all,
                         cudaFuncAttributeMaxDynamicSharedMemorySize, TG_SMEM);

    // fp16 conversion of weights only (+ dpow table); x stays fp32
    convert_kernel<<<256, 256>>>(wk, wv, wq, wg, wo);

    // merged front-end: q-proj + k/v-proj + gate in one launch (x converted
    // to fp16 inside the A-loader)
    proj_all<<<800, 256, TG_SMEM>>>(x);

    // chunked linear-attention decomposition of the scan
    chunkw_kernel<<<dim3(NHH, NC), 256>>>();
    scan_kernel<<<128, 256>>>();
    retrieve_tc<<<dim3(NHH, NC, BB), 256, RT_SMEM>>>();

    // out = x + retrieved @ w_out^T
    tgemm_out<<<dim3(6, 128), 256, TG_SMEM>>>(x, out);
}